// round 15
// baseline (speedup 1.0000x reference)
#include <cuda_runtime.h>
#include <cuda_fp16.h>
#include <stdint.h>

namespace pks {

constexpr int    KS = 32768;           // knowledge size
constexpr int    H  = 1024;            // hidden
constexpr int    QD = 512;             // query dim
constexpr int    MQ = 8192;            // 4 * 2048 query rows
constexpr int    CAP = 512;            // max candidates per row
constexpr size_t SZ_Q  = (size_t)MQ * QD;
constexpr size_t SZ_KB = (size_t)KS * H;
constexpr size_t SZ_K  = (size_t)KS * QD;
constexpr size_t SZ_S  = (size_t)MQ * KS;
constexpr size_t SZ_T  = (size_t)MQ * H;

// -------- scratch: __device__ globals (no runtime allocation) --------
__device__ __half g_qh [SZ_Q],  g_ql [SZ_Q];    // queries split
__device__ __half g_kbh[SZ_KB];                 // knowledge bank fp16 (hi only)
__device__ __half g_wkt_h[(size_t)QD * H];      // Wk^T fp16 (keys screen)
__device__ __half g_wk_h[(size_t)H * QD], g_wk_l[(size_t)H * QD]; // Wk split (Z GEMM)
__device__ __half g_wvt_h[(size_t)H * H], g_wvt_l[(size_t)H * H]; // Wv^T split
__device__ __half g_kh [SZ_K];                  // keys fp16 (screen only)
__device__ float  g_Z  [SZ_T];                  // Z = Q @ Wk^T  [MQ, H] fp32
__device__ __half g_Th [SZ_T],  g_Tl [SZ_T];    // T = P*KB split [MQ, H]
__device__ __half g_Sh [SZ_S];                  // approx scores fp16 [MQ, KS]
__device__ int    g_sidx[(size_t)MQ * CAP];     // candidate column indices
__device__ int    g_scnt[MQ];                   // per-row candidate count

__device__ __forceinline__ uint32_t cvta_s(const void* p) {
    return (uint32_t)__cvta_generic_to_shared(p);
}
__device__ __forceinline__ void ldsm4(uint32_t r[4], uint32_t a) {
    asm volatile("ldmatrix.sync.aligned.m8n8.x4.shared.b16 {%0,%1,%2,%3},[%4];\n"
                 : "=r"(r[0]), "=r"(r[1]), "=r"(r[2]), "=r"(r[3]) : "r"(a));
}
__device__ __forceinline__ void mma16816(float c[4], const uint32_t a[4], const uint32_t b[2]) {
    asm volatile("mma.sync.aligned.m16n8k16.row.col.f32.f16.f16.f32 "
                 "{%0,%1,%2,%3},{%4,%5,%6,%7},{%8,%9},{%0,%1,%2,%3};\n"
                 : "+f"(c[0]), "+f"(c[1]), "+f"(c[2]), "+f"(c[3])
                 : "r"(a[0]), "r"(a[1]), "r"(a[2]), "r"(a[3]), "r"(b[0]), "r"(b[1]));
}
__device__ __forceinline__ void split2(float x, float y, __half2& hi, __half2& lo) {
    __half hx = __float2half_rn(x), hy = __float2half_rn(y);
    hi = __halves2half2(hx, hy);
    lo = __halves2half2(__float2half_rn(x - __half2float(hx)),
                        __float2half_rn(y - __half2float(hy)));
}
__device__ __forceinline__ void cp16(uint32_t s, const void* g) {
    asm volatile("cp.async.cg.shared.global [%0], [%1], 16;\n" :: "r"(s), "l"(g));
}
__device__ __forceinline__ void cp_commit() { asm volatile("cp.async.commit_group;\n"); }
template<int N> __device__ __forceinline__ void cp_wait() {
    asm volatile("cp.async.wait_group %0;\n" :: "n"(N));
}

// =====================================================================
// Prep kernels
// =====================================================================
__global__ void split_kernel(const float4* __restrict__ src,
                             uint2* __restrict__ hi, uint2* __restrict__ lo, int n4) {
    int i = blockIdx.x * 256 + threadIdx.x;
    if (i >= n4) return;
    float4 f = src[i];
    __half2 h0, l0, h1, l1;
    split2(f.x, f.y, h0, l0);
    split2(f.z, f.w, h1, l1);
    uint2 uh, ul;
    uh.x = *(unsigned*)&h0; uh.y = *(unsigned*)&h1;
    ul.x = *(unsigned*)&l0; ul.y = *(unsigned*)&l1;
    hi[i] = uh; lo[i] = ul;
}

__global__ void tohalf_kernel(const float4* __restrict__ src,
                              uint2* __restrict__ hi, int n4) {
    int i = blockIdx.x * 256 + threadIdx.x;
    if (i >= n4) return;
    float4 f = src[i];
    __half2 h0 = __floats2half2_rn(f.x, f.y);
    __half2 h1 = __floats2half2_rn(f.z, f.w);
    uint2 uh;
    uh.x = *(unsigned*)&h0; uh.y = *(unsigned*)&h1;
    hi[i] = uh;
}

// W [Kin, Nout] -> Wt fp16 (hi only) [Nout, Kin]
__global__ void thalf_kernel(const float* __restrict__ W,
                             __half* __restrict__ th, int Kin, int Nout) {
    int i = blockIdx.x * 256 + threadIdx.x;
    if (i >= Kin * Nout) return;
    int k = i / Nout, n = i - k * Nout;
    th[(size_t)n * Kin + k] = __float2half_rn(W[i]);
}

// W [Kin, Nout] -> Wt hi/lo [Nout, Kin]
__global__ void tsplit_kernel(const float* __restrict__ W,
                              __half* __restrict__ th, __half* __restrict__ tl,
                              int Kin, int Nout) {
    int i = blockIdx.x * 256 + threadIdx.x;
    if (i >= Kin * Nout) return;
    int k = i / Nout, n = i - k * Nout;
    float x = W[i];
    __half h = __float2half_rn(x);
    th[(size_t)n * Kin + k] = h;
    tl[(size_t)n * Kin + k] = __float2half_rn(x - __half2float(h));
}

// =====================================================================
// Unified fp16 TN GEMM, STAGES-deep cp.async pipeline.
// NPROD 3: ah*bh + ah*bl + al*bh   NPROD 2: ah*bh + ah*bl   NPROD 1: ah*bh
// EPI 0: split fp16 + bias   EPI 1: fp16 + bias   EPI 2: fp32 + bias
// Per-stage smem block: [A, B, (Al), (Bl)] contiguous.
// =====================================================================
template<int NPROD, int EPI, int BK, int STAGES>
__global__ __launch_bounds__(256, 2) void gemm_tn(
    const __half* __restrict__ Ah, const __half* __restrict__ Al,
    const __half* __restrict__ Bh, const __half* __restrict__ Bl,
    int K, const float* __restrict__ bias,
    float* __restrict__ fout, __half* __restrict__ hout0,
    __half* __restrict__ hout1, int ldc)
{
    extern __shared__ __half smem[];
    constexpr int SROW = BK + 8;
    constexpr uint32_t TB = 128u * SROW * 2u;
    constexpr int OP = (NPROD == 3) ? 4 : (NPROD == 2 ? 3 : 2);
    constexpr uint32_t SSZ = OP * TB;                 // bytes per stage
    constexpr int CPR = BK / 8;
    constexpr int NCH = BK / 16;

    const int tid = threadIdx.x, lane = tid & 31, wid = tid >> 5;
    const int wm = wid >> 2, wn = wid & 3;
    const int m0 = blockIdx.y * 128, n0 = blockIdx.x * 128;

    const uint32_t base = cvta_s(smem);
    // within-stage offsets
    constexpr uint32_t oA = 0, oB = TB;
    constexpr uint32_t oAl = 2 * TB;                       // NPROD3
    constexpr uint32_t oBl = (NPROD == 3) ? 3 * TB : 2 * TB; // NPROD>=2

    float c[4][4][4] = {};

    auto issue = [&](int kc, int s) {
        const uint32_t sb = base + (uint32_t)s * SSZ;
#pragma unroll
        for (int j = 0; j < NCH; j++) {
            int idx = tid + j * 256;
            int r = idx / CPR, ch = idx % CPR;
            uint32_t so = (uint32_t)r * (SROW * 2) + ch * 16;
            cp16(sb + oA + so, &Ah[(size_t)(m0 + r) * K + kc + ch * 8]);
            cp16(sb + oB + so, &Bh[(size_t)(n0 + r) * K + kc + ch * 8]);
            if (NPROD == 3)
                cp16(sb + oAl + so, &Al[(size_t)(m0 + r) * K + kc + ch * 8]);
            if (NPROD >= 2)
                cp16(sb + oBl + so, &Bl[(size_t)(n0 + r) * K + kc + ch * 8]);
        }
    };

    const uint32_t aoff = 2u * ((wm * 64 + (lane & 15)) * SROW + ((lane >> 4) << 3));
    const uint32_t boff = 2u * ((wn * 32 + (lane & 7) + ((lane >> 4) << 3)) * SROW
                                + (((lane >> 3) & 1) << 3));

    const int niter = K / BK;
#pragma unroll
    for (int s = 0; s < STAGES - 1; s++) {
        if (s < niter) issue(s * BK, s);
        cp_commit();
    }

    for (int it = 0; it < niter; ++it) {
        if (it + STAGES - 1 < niter) issue((it + STAGES - 1) * BK, (it + STAGES - 1) % STAGES);
        cp_commit();
        cp_wait<STAGES - 1>();
        __syncthreads();

        const uint32_t sb = base + (uint32_t)(it % STAGES) * SSZ;
#pragma unroll
        for (int ks = 0; ks < BK; ks += 16) {
            uint32_t ah[4][4], bh[2][4], al[4][4], bl[2][4];
#pragma unroll
            for (int mi = 0; mi < 4; mi++) {
                ldsm4(ah[mi], sb + oA + aoff + 2u * (mi * 16 * SROW + ks));
                if (NPROD == 3) ldsm4(al[mi], sb + oAl + aoff + 2u * (mi * 16 * SROW + ks));
            }
#pragma unroll
            for (int nb = 0; nb < 2; nb++) {
                ldsm4(bh[nb], sb + oB + boff + 2u * (nb * 16 * SROW + ks));
                if (NPROD >= 2) ldsm4(bl[nb], sb + oBl + boff + 2u * (nb * 16 * SROW + ks));
            }
#pragma unroll
            for (int mi = 0; mi < 4; mi++)
#pragma unroll
                for (int nj = 0; nj < 4; nj++) {
                    const uint32_t* bp = &bh[nj >> 1][(nj & 1) * 2];
                    mma16816(c[mi][nj], ah[mi], bp);
                    if (NPROD >= 2) {
                        const uint32_t* blp = &bl[nj >> 1][(nj & 1) * 2];
                        mma16816(c[mi][nj], ah[mi], blp);
                    }
                    if (NPROD == 3) mma16816(c[mi][nj], al[mi], bp);
                }
        }
        __syncthreads();
    }

    const int g = lane >> 2, t = lane & 3;
#pragma unroll
    for (int mi = 0; mi < 4; mi++)
#pragma unroll
        for (int nj = 0; nj < 4; nj++) {
            const int n = n0 + wn * 32 + nj * 8 + t * 2;
            float b0 = 0.f, b1 = 0.f;
            if (bias) { b0 = __ldg(&bias[n]); b1 = __ldg(&bias[n + 1]); }
#pragma unroll
            for (int h = 0; h < 2; h++) {
                const int m = m0 + wm * 64 + mi * 16 + g + h * 8;
                const float v0 = c[mi][nj][h * 2 + 0] + b0;
                const float v1 = c[mi][nj][h * 2 + 1] + b1;
                if (EPI == 0) {
                    __half h0 = __float2half_rn(v0), h1 = __float2half_rn(v1);
                    *(__half2*)&hout0[(size_t)m * ldc + n] = __halves2half2(h0, h1);
                    *(__half2*)&hout1[(size_t)m * ldc + n] = __halves2half2(
                        __float2half_rn(v0 - __half2float(h0)),
                        __float2half_rn(v1 - __half2float(h1)));
                } else if (EPI == 1) {
                    *(__half2*)&hout0[(size_t)m * ldc + n] = __floats2half2_rn(v0, v1);
                } else {
                    *(float2*)&fout[(size_t)m * ldc + n] = make_float2(v0, v1);
                }
            }
        }
}

// =====================================================================
// Select: per row, max of approx scores, compact cols with s >= mx-12.4
// =====================================================================
__global__ __launch_bounds__(1024) void select_kernel(
    const __half* __restrict__ Sh, int* __restrict__ sidx, int* __restrict__ scnt)
{
    __shared__ float red[32];
    __shared__ int wsum[32], wbase[32];
    const size_t row = blockIdx.x;
    const int t = threadIdx.x, lane = t & 31, warp = t >> 5;
    const uint2* src = (const uint2*)(Sh + row * (size_t)KS);
    float v[32];
#pragma unroll
    for (int j = 0; j < 8; j++) {
        uint2 u = src[j * 1024 + t];
        float2 fa = __half22float2(*(__half2*)&u.x);
        float2 fb = __half22float2(*(__half2*)&u.y);
        v[j * 4 + 0] = fa.x; v[j * 4 + 1] = fa.y;
        v[j * 4 + 2] = fb.x; v[j * 4 + 3] = fb.y;
    }
    float mx = v[0];
#pragma unroll
    for (int i = 1; i < 32; i++) mx = fmaxf(mx, v[i]);
#pragma unroll
    for (int o = 16; o; o >>= 1) mx = fmaxf(mx, __shfl_xor_sync(0xffffffffu, mx, o));
    if (lane == 0) red[warp] = mx;
    __syncthreads();
    if (t < 32) {
        float m2 = red[t];
#pragma unroll
        for (int o = 16; o; o >>= 1) m2 = fmaxf(m2, __shfl_xor_sync(0xffffffffu, m2, o));
        if (t == 0) red[0] = m2;
    }
    __syncthreads();
    const float th = red[0] - 12.4f;

    unsigned flags = 0;
    int lc = 0;
#pragma unroll
    for (int i = 0; i < 32; i++)
        if (v[i] >= th) { flags |= (1u << i); lc++; }

    int x = lc;
#pragma unroll
    for (int o = 1; o < 32; o <<= 1) {
        int y = __shfl_up_sync(0xffffffffu, x, o);
        if (lane >= o) x += y;
    }
    if (lane == 31) wsum[warp] = x;
    __syncthreads();
    if (t < 32) {
        int y = wsum[t];
        int inc = y;
#pragma unroll
        for (int o = 1; o < 32; o <<= 1) {
            int z = __shfl_up_sync(0xffffffffu, inc, o);
            if (t >= o) inc += z;
        }
        wbase[t] = inc - y;
        if (t == 31) wsum[0] = inc;
    }
    __syncthreads();
    int pos = wbase[warp] + (x - lc);
    const int total = wsum[0];

    int* ib = sidx + row * (size_t)CAP;
#pragma unroll
    for (int i = 0; i < 32; i++) {
        if (flags & (1u << i)) {
            if (pos < CAP) ib[pos] = (i >> 2) * 4096 + t * 4 + (i & 3);
            pos++;
        }
    }
    if (t == 0) scnt[row] = (total < CAP) ? total : CAP;
}

// =====================================================================
// Rescore via Z = Wk q: s_c = Z[row]·KB[idx_c]  (q·bk cancels in softmax)
// + softmax + weighted KB gather.
// =====================================================================
__global__ __launch_bounds__(256) void rescore_gather_kernel(
    const float* __restrict__ Z, const float* __restrict__ kb,
    const int* __restrict__ sidx, const int* __restrict__ scnt,
    __half* __restrict__ Th, __half* __restrict__ Tl)
{
    __shared__ float zs[H];
    __shared__ float sex[CAP];
    __shared__ int   idxs[CAP];
    __shared__ float red[8];
    const size_t row = blockIdx.x;
    const int t = threadIdx.x, lane = t & 31, wid = t >> 5;
    const int cnt = scnt[row];

#pragma unroll
    for (int j = 0; j < 4; j++) zs[t + j * 256] = Z[row * H + t + j * 256];
    for (int c = t; c < cnt; c += 256) idxs[c] = sidx[row * (size_t)CAP + c];
    __syncthreads();

    for (int c = wid; c < cnt; c += 8) {
        const float4* k4 = (const float4*)(kb + (size_t)idxs[c] * H);
        float s = 0.f;
#pragma unroll
        for (int j = lane; j < H / 4; j += 32) {
            const float4 k = k4[j];
            s += zs[4 * j] * k.x + zs[4 * j + 1] * k.y
               + zs[4 * j + 2] * k.z + zs[4 * j + 3] * k.w;
        }
#pragma unroll
        for (int o = 16; o; o >>= 1) s += __shfl_xor_sync(0xffffffffu, s, o);
        if (lane == 0) sex[c] = s;
    }
    __syncthreads();

    float mx = -1e30f;
    for (int c = t; c < cnt; c += 256) mx = fmaxf(mx, sex[c]);
#pragma unroll
    for (int o = 16; o; o >>= 1) mx = fmaxf(mx, __shfl_xor_sync(0xffffffffu, mx, o));
    if (lane == 0) red[wid] = mx;
    __syncthreads();
    if (t == 0) {
        float m = red[0];
#pragma unroll
        for (int i = 1; i < 8; i++) m = fmaxf(m, red[i]);
        red[0] = m;
    }
    __syncthreads();
    mx = red[0];
    __syncthreads();

    float ps = 0.f;
    for (int c = t; c < cnt; c += 256) {
        float e = __expf(sex[c] - mx);
        sex[c] = e;
        ps += e;
    }
#pragma unroll
    for (int o = 16; o; o >>= 1) ps += __shfl_xor_sync(0xffffffffu, ps, o);
    if (lane == 0) red[wid] = ps;
    __syncthreads();
    if (t == 0) {
        float s = 0.f;
#pragma unroll
        for (int i = 0; i < 8; i++) s += red[i];
        red[0] = s;
    }
    __syncthreads();
    const float inv = 1.0f / red[0];

    float a0 = 0.f, a1 = 0.f, a2 = 0.f, a3 = 0.f;
    for (int c = 0; c < cnt; c++) {
        const float w = sex[c] * inv;
        if (w < 5.96e-8f) continue;
        const float4 k4 = *(const float4*)&kb[(size_t)idxs[c] * H + t * 4];
        a0 += w * k4.x; a1 += w * k4.y; a2 += w * k4.z; a3 += w * k4.w;
    }
    __half2 h01, l01, h23, l23;
    split2(a0, a1, h01, l01);
    split2(a2, a3, h23, l23);
    uint2 uh, ul;
    uh.x = *(unsigned*)&h01; uh.y = *(unsigned*)&h23;
    ul.x = *(unsigned*)&l01; ul.y = *(unsigned*)&l23;
    *(uint2*)&Th[row * (size_t)H + t * 4] = uh;
    *(uint2*)&Tl[row * (size_t)H + t * 4] = ul;
}

} // namespace pks

#define PKS_SYM(p, s) { void* _t = nullptr; cudaGetSymbolAddress(&_t, s); p = (decltype(p))_t; }

extern "C" void kernel_launch(void* const* d_in, const int* in_sizes, int n_in,
                              void* d_out, int out_size) {
    using namespace pks;
    const float* q  = (const float*)d_in[0];
    const float* kb = (const float*)d_in[1];
    const float* Wk = (const float*)d_in[2];
    const float* bk = (const float*)d_in[3];
    const float* Wv = (const float*)d_in[4];
    const float* bv = (const float*)d_in[5];
    float* out = (float*)d_out;

    __half *qh, *ql, *kbh, *wkth, *wkh, *wkl, *wvth, *wvtl, *kh, *Th, *Tl, *Sh;
    float* Z;
    int *sidx, *scnt;
    PKS_SYM(qh, g_qh);      PKS_SYM(ql, g_ql);
    PKS_SYM(kbh, g_kbh);
    PKS_SYM(wkth, g_wkt_h);
    PKS_SYM(wkh, g_wk_h);   PKS_SYM(wkl, g_wk_l);
    PKS_SYM(wvth, g_wvt_h); PKS_SYM(wvtl, g_wvt_l);
    PKS_SYM(kh, g_kh);      PKS_SYM(Z, g_Z);
    PKS_SYM(Th, g_Th);      PKS_SYM(Tl, g_Tl);
    PKS_SYM(Sh, g_Sh);
    PKS_SYM(sidx, g_sidx);  PKS_SYM(scnt, g_scnt);

    const int smem3 = 2 * 4 * 128 * 40 * 2;   // 81920 (NPROD3, BK32, S2)
    const int smem2 = 2 * 3 * 128 * 40 * 2;   // 61440 (NPROD2, BK32, S2)
    const int smemK = 2 * 2 * 128 * 72 * 2;   // 73728 (NPROD1, BK64, S2) keys
    const int smemS = 3 * 2 * 128 * 40 * 2;   // 61440 (NPROD1, BK32, S3) screen
    cudaFuncSetAttribute(gemm_tn<3, 2, 32, 2>, cudaFuncAttributeMaxDynamicSharedMemorySize, smem3);
    cudaFuncSetAttribute(gemm_tn<2, 2, 32, 2>, cudaFuncAttributeMaxDynamicSharedMemorySize, smem2);
    cudaFuncSetAttribute(gemm_tn<1, 1, 64, 2>, cudaFuncAttributeMaxDynamicSharedMemorySize, smemK);
    cudaFuncSetAttribute(gemm_tn<1, 1, 32, 3>, cudaFuncAttributeMaxDynamicSharedMemorySize, smemS);

    // 1) prep
    {
        int n4 = (int)(SZ_Q / 4);
        split_kernel<<<(n4 + 255) / 256, 256>>>((const float4*)q, (uint2*)qh, (uint2*)ql, n4);
    }
    {
        int n4 = (int)(SZ_KB / 4);
        tohalf_kernel<<<(n4 + 255) / 256, 256>>>((const float4*)kb, (uint2*)kbh, n4);
    }
    thalf_kernel<<<(H * QD + 255) / 256, 256>>>(Wk, wkth, H, QD);         // Wk^T fp16 [QD, H]
    {
        int n4 = (int)((size_t)H * QD / 4);                                // Wk split [H, QD] (as given)
        split_kernel<<<(n4 + 255) / 256, 256>>>((const float4*)Wk, (uint2*)wkh, (uint2*)wkl, n4);
    }
    tsplit_kernel<<<(H * H + 255) / 256, 256>>>(Wv, wvth, wvtl, H, H);    // Wv^T split [H, H]

    // 2) keys = KB @ Wk + bk (single product, fp16 out; screen only) [KS, QD]
    gemm_tn<1, 1, 64, 2><<<dim3(QD / 128, KS / 128), 256, smemK>>>(
        kbh, nullptr, wkth, nullptr, H, bk, nullptr, kh, nullptr, QD);

    // 3) Z = Q @ Wk^T (split-3, fp32, no bias — q·bk cancels in softmax) [MQ, H]
    gemm_tn<3, 2, 32, 2><<<dim3(H / 128, MQ / 128), 256, smem3>>>(
        qh, ql, wkh, wkl, QD, nullptr, Z, nullptr, nullptr, H);

    // 4) screen scores = qh @ kh^T (single product, 3-stage, fp16 out) [MQ, KS]
    gemm_tn<1, 1, 32, 3><<<dim3(KS / 128, MQ / 128), 256, smemS>>>(
        qh, nullptr, kh, nullptr, QD, nullptr, nullptr, Sh, nullptr, KS);

    // 5) select candidates (s >= rowmax - 12.4)
    select_kernel<<<MQ, 1024>>>(Sh, sidx, scnt);

    // 6) rescore via Z·KB + softmax + weighted KB gather -> T split
    rescore_gather_kernel<<<MQ, 256>>>(Z, kb, sidx, scnt, Th, Tl);

    // 7) out = T @ Wv + bv (2-product split, fp32) [MQ, H]
    gemm_tn<2, 2, 32, 2><<<dim3(H / 128, MQ / 128), 256, smem2>>>(
        Th, Tl, wvth, wvtl, H, bv, out, nullptr, nullptr, H);
}

// round 17
// speedup vs baseline: 1.0696x; 1.0696x over previous
#include <cuda_runtime.h>
#include <cuda_fp16.h>
#include <stdint.h>

namespace pks {

constexpr int    KS = 32768;           // knowledge size
constexpr int    H  = 1024;            // hidden
constexpr int    QD = 512;             // query dim
constexpr int    MQ = 8192;            // 4 * 2048 query rows
constexpr int    CAP = 512;            // max candidates per row
constexpr size_t SZ_Q  = (size_t)MQ * QD;
constexpr size_t SZ_KB = (size_t)KS * H;
constexpr size_t SZ_K  = (size_t)KS * QD;
constexpr size_t SZ_S  = (size_t)MQ * KS;
constexpr size_t SZ_T  = (size_t)MQ * H;

// -------- scratch: __device__ globals (no runtime allocation) --------
__device__ __half g_qh [SZ_Q],  g_ql [SZ_Q];    // queries split
__device__ __half g_kbh[SZ_KB];                 // knowledge bank fp16 (hi only)
__device__ __half g_wkt_h[(size_t)QD * H];      // Wk^T fp16 (keys screen)
__device__ __half g_wk_h[(size_t)H * QD], g_wk_l[(size_t)H * QD]; // Wk split (Z GEMM)
__device__ __half g_wvt_h[(size_t)H * H], g_wvt_l[(size_t)H * H]; // Wv^T split
__device__ __half g_kh [SZ_K];                  // keys fp16 (screen only)
__device__ float  g_Z  [SZ_T];                  // Z = Q @ Wk^T  [MQ, H] fp32
__device__ __half g_Th [SZ_T],  g_Tl [SZ_T];    // T = P*KB split [MQ, H]
__device__ __half g_Sh [SZ_S];                  // approx scores fp16 [MQ, KS]
__device__ int    g_sidx[(size_t)MQ * CAP];     // candidate column indices
__device__ int    g_scnt[MQ];                   // per-row candidate count

__device__ __forceinline__ uint32_t cvta_s(const void* p) {
    return (uint32_t)__cvta_generic_to_shared(p);
}
__device__ __forceinline__ void ldsm4(uint32_t r[4], uint32_t a) {
    asm volatile("ldmatrix.sync.aligned.m8n8.x4.shared.b16 {%0,%1,%2,%3},[%4];\n"
                 : "=r"(r[0]), "=r"(r[1]), "=r"(r[2]), "=r"(r[3]) : "r"(a));
}
__device__ __forceinline__ void mma16816(float c[4], const uint32_t a[4], const uint32_t b[2]) {
    asm volatile("mma.sync.aligned.m16n8k16.row.col.f32.f16.f16.f32 "
                 "{%0,%1,%2,%3},{%4,%5,%6,%7},{%8,%9},{%0,%1,%2,%3};\n"
                 : "+f"(c[0]), "+f"(c[1]), "+f"(c[2]), "+f"(c[3])
                 : "r"(a[0]), "r"(a[1]), "r"(a[2]), "r"(a[3]), "r"(b[0]), "r"(b[1]));
}
__device__ __forceinline__ void split2(float x, float y, __half2& hi, __half2& lo) {
    __half hx = __float2half_rn(x), hy = __float2half_rn(y);
    hi = __halves2half2(hx, hy);
    lo = __halves2half2(__float2half_rn(x - __half2float(hx)),
                        __float2half_rn(y - __half2float(hy)));
}
__device__ __forceinline__ void cp16(uint32_t s, const void* g) {
    asm volatile("cp.async.cg.shared.global [%0], [%1], 16;\n" :: "r"(s), "l"(g));
}
__device__ __forceinline__ void cp_commit() { asm volatile("cp.async.commit_group;\n"); }
template<int N> __device__ __forceinline__ void cp_wait() {
    asm volatile("cp.async.wait_group %0;\n" :: "n"(N));
}

// =====================================================================
// Prep kernels
// =====================================================================
__global__ void split_kernel(const float4* __restrict__ src,
                             uint2* __restrict__ hi, uint2* __restrict__ lo, int n4) {
    int i = blockIdx.x * 256 + threadIdx.x;
    if (i >= n4) return;
    float4 f = src[i];
    __half2 h0, l0, h1, l1;
    split2(f.x, f.y, h0, l0);
    split2(f.z, f.w, h1, l1);
    uint2 uh, ul;
    uh.x = *(unsigned*)&h0; uh.y = *(unsigned*)&h1;
    ul.x = *(unsigned*)&l0; ul.y = *(unsigned*)&l1;
    hi[i] = uh; lo[i] = ul;
}

__global__ void tohalf_kernel(const float4* __restrict__ src,
                              uint2* __restrict__ hi, int n4) {
    int i = blockIdx.x * 256 + threadIdx.x;
    if (i >= n4) return;
    float4 f = src[i];
    __half2 h0 = __floats2half2_rn(f.x, f.y);
    __half2 h1 = __floats2half2_rn(f.z, f.w);
    uint2 uh;
    uh.x = *(unsigned*)&h0; uh.y = *(unsigned*)&h1;
    hi[i] = uh;
}

// W [Kin, Nout] -> Wt fp16 (hi only) [Nout, Kin]
__global__ void thalf_kernel(const float* __restrict__ W,
                             __half* __restrict__ th, int Kin, int Nout) {
    int i = blockIdx.x * 256 + threadIdx.x;
    if (i >= Kin * Nout) return;
    int k = i / Nout, n = i - k * Nout;
    th[(size_t)n * Kin + k] = __float2half_rn(W[i]);
}

// W [Kin, Nout] -> Wt hi/lo [Nout, Kin]
__global__ void tsplit_kernel(const float* __restrict__ W,
                              __half* __restrict__ th, __half* __restrict__ tl,
                              int Kin, int Nout) {
    int i = blockIdx.x * 256 + threadIdx.x;
    if (i >= Kin * Nout) return;
    int k = i / Nout, n = i - k * Nout;
    float x = W[i];
    __half h = __float2half_rn(x);
    th[(size_t)n * Kin + k] = h;
    tl[(size_t)n * Kin + k] = __float2half_rn(x - __half2float(h));
}

// =====================================================================
// Unified fp16 TN GEMM, STAGES-deep cp.async pipeline.
// NPROD 3: ah*bh + ah*bl + al*bh   NPROD 2: ah*bh + ah*bl   NPROD 1: ah*bh
// EPI 0: split fp16 + bias   EPI 1: fp16 + bias   EPI 2: fp32 + bias
// Per-stage smem block: [A, B, (Al), (Bl)] contiguous.
// =====================================================================
template<int NPROD, int EPI, int BK, int STAGES>
__global__ __launch_bounds__(256, 2) void gemm_tn(
    const __half* __restrict__ Ah, const __half* __restrict__ Al,
    const __half* __restrict__ Bh, const __half* __restrict__ Bl,
    int K, const float* __restrict__ bias,
    float* __restrict__ fout, __half* __restrict__ hout0,
    __half* __restrict__ hout1, int ldc)
{
    extern __shared__ __half smem[];
    constexpr int SROW = BK + 8;
    constexpr uint32_t TB = 128u * SROW * 2u;
    constexpr int OP = (NPROD == 3) ? 4 : (NPROD == 2 ? 3 : 2);
    constexpr uint32_t SSZ = OP * TB;                 // bytes per stage
    constexpr int CPR = BK / 8;
    constexpr int NCH = BK / 16;

    const int tid = threadIdx.x, lane = tid & 31, wid = tid >> 5;
    const int wm = wid >> 2, wn = wid & 3;
    const int m0 = blockIdx.y * 128, n0 = blockIdx.x * 128;

    const uint32_t base = cvta_s(smem);
    constexpr uint32_t oA = 0, oB = TB;
    constexpr uint32_t oAl = 2 * TB;                         // NPROD3
    constexpr uint32_t oBl = (NPROD == 3) ? 3 * TB : 2 * TB; // NPROD>=2

    float c[4][4][4] = {};

    auto issue = [&](int kc, int s) {
        const uint32_t sb = base + (uint32_t)s * SSZ;
#pragma unroll
        for (int j = 0; j < NCH; j++) {
            int idx = tid + j * 256;
            int r = idx / CPR, ch = idx % CPR;
            uint32_t so = (uint32_t)r * (SROW * 2) + ch * 16;
            cp16(sb + oA + so, &Ah[(size_t)(m0 + r) * K + kc + ch * 8]);
            cp16(sb + oB + so, &Bh[(size_t)(n0 + r) * K + kc + ch * 8]);
            if (NPROD == 3)
                cp16(sb + oAl + so, &Al[(size_t)(m0 + r) * K + kc + ch * 8]);
            if (NPROD >= 2)
                cp16(sb + oBl + so, &Bl[(size_t)(n0 + r) * K + kc + ch * 8]);
        }
    };

    const uint32_t aoff = 2u * ((wm * 64 + (lane & 15)) * SROW + ((lane >> 4) << 3));
    const uint32_t boff = 2u * ((wn * 32 + (lane & 7) + ((lane >> 4) << 3)) * SROW
                                + (((lane >> 3) & 1) << 3));

    const int niter = K / BK;
#pragma unroll
    for (int s = 0; s < STAGES - 1; s++) {
        if (s < niter) issue(s * BK, s);
        cp_commit();
    }

    for (int it = 0; it < niter; ++it) {
        if (it + STAGES - 1 < niter) issue((it + STAGES - 1) * BK, (it + STAGES - 1) % STAGES);
        cp_commit();
        cp_wait<STAGES - 1>();
        __syncthreads();

        const uint32_t sb = base + (uint32_t)(it % STAGES) * SSZ;
#pragma unroll
        for (int ks = 0; ks < BK; ks += 16) {
            uint32_t ah[4][4], bh[2][4], al[4][4], bl[2][4];
#pragma unroll
            for (int mi = 0; mi < 4; mi++) {
                ldsm4(ah[mi], sb + oA + aoff + 2u * (mi * 16 * SROW + ks));
                if (NPROD == 3) ldsm4(al[mi], sb + oAl + aoff + 2u * (mi * 16 * SROW + ks));
            }
#pragma unroll
            for (int nb = 0; nb < 2; nb++) {
                ldsm4(bh[nb], sb + oB + boff + 2u * (nb * 16 * SROW + ks));
                if (NPROD >= 2) ldsm4(bl[nb], sb + oBl + boff + 2u * (nb * 16 * SROW + ks));
            }
#pragma unroll
            for (int mi = 0; mi < 4; mi++)
#pragma unroll
                for (int nj = 0; nj < 4; nj++) {
                    const uint32_t* bp = &bh[nj >> 1][(nj & 1) * 2];
                    mma16816(c[mi][nj], ah[mi], bp);
                    if (NPROD >= 2) {
                        const uint32_t* blp = &bl[nj >> 1][(nj & 1) * 2];
                        mma16816(c[mi][nj], ah[mi], blp);
                    }
                    if (NPROD == 3) mma16816(c[mi][nj], al[mi], bp);
                }
        }
        __syncthreads();
    }

    const int g = lane >> 2, t = lane & 3;
#pragma unroll
    for (int mi = 0; mi < 4; mi++)
#pragma unroll
        for (int nj = 0; nj < 4; nj++) {
            const int n = n0 + wn * 32 + nj * 8 + t * 2;
            float b0 = 0.f, b1 = 0.f;
            if (bias) { b0 = __ldg(&bias[n]); b1 = __ldg(&bias[n + 1]); }
#pragma unroll
            for (int h = 0; h < 2; h++) {
                const int m = m0 + wm * 64 + mi * 16 + g + h * 8;
                const float v0 = c[mi][nj][h * 2 + 0] + b0;
                const float v1 = c[mi][nj][h * 2 + 1] + b1;
                if (EPI == 0) {
                    __half h0 = __float2half_rn(v0), h1 = __float2half_rn(v1);
                    *(__half2*)&hout0[(size_t)m * ldc + n] = __halves2half2(h0, h1);
                    *(__half2*)&hout1[(size_t)m * ldc + n] = __halves2half2(
                        __float2half_rn(v0 - __half2float(h0)),
                        __float2half_rn(v1 - __half2float(h1)));
                } else if (EPI == 1) {
                    *(__half2*)&hout0[(size_t)m * ldc + n] = __floats2half2_rn(v0, v1);
                } else {
                    *(float2*)&fout[(size_t)m * ldc + n] = make_float2(v0, v1);
                }
            }
        }
}

// =====================================================================
// Select: per row, max of approx scores, compact cols with s >= mx-12.4
// =====================================================================
__global__ __launch_bounds__(1024) void select_kernel(
    const __half* __restrict__ Sh, int* __restrict__ sidx, int* __restrict__ scnt)
{
    __shared__ float red[32];
    __shared__ int wsum[32], wbase[32];
    const size_t row = blockIdx.x;
    const int t = threadIdx.x, lane = t & 31, warp = t >> 5;
    const uint2* src = (const uint2*)(Sh + row * (size_t)KS);
    float v[32];
#pragma unroll
    for (int j = 0; j < 8; j++) {
        uint2 u = src[j * 1024 + t];
        float2 fa = __half22float2(*(__half2*)&u.x);
        float2 fb = __half22float2(*(__half2*)&u.y);
        v[j * 4 + 0] = fa.x; v[j * 4 + 1] = fa.y;
        v[j * 4 + 2] = fb.x; v[j * 4 + 3] = fb.y;
    }
    float mx = v[0];
#pragma unroll
    for (int i = 1; i < 32; i++) mx = fmaxf(mx, v[i]);
#pragma unroll
    for (int o = 16; o; o >>= 1) mx = fmaxf(mx, __shfl_xor_sync(0xffffffffu, mx, o));
    if (lane == 0) red[warp] = mx;
    __syncthreads();
    if (t < 32) {
        float m2 = red[t];
#pragma unroll
        for (int o = 16; o; o >>= 1) m2 = fmaxf(m2, __shfl_xor_sync(0xffffffffu, m2, o));
        if (t == 0) red[0] = m2;
    }
    __syncthreads();
    const float th = red[0] - 12.4f;

    unsigned flags = 0;
    int lc = 0;
#pragma unroll
    for (int i = 0; i < 32; i++)
        if (v[i] >= th) { flags |= (1u << i); lc++; }

    int x = lc;
#pragma unroll
    for (int o = 1; o < 32; o <<= 1) {
        int y = __shfl_up_sync(0xffffffffu, x, o);
        if (lane >= o) x += y;
    }
    if (lane == 31) wsum[warp] = x;
    __syncthreads();
    if (t < 32) {
        int y = wsum[t];
        int inc = y;
#pragma unroll
        for (int o = 1; o < 32; o <<= 1) {
            int z = __shfl_up_sync(0xffffffffu, inc, o);
            if (t >= o) inc += z;
        }
        wbase[t] = inc - y;
        if (t == 31) wsum[0] = inc;
    }
    __syncthreads();
    int pos = wbase[warp] + (x - lc);
    const int total = wsum[0];

    int* ib = sidx + row * (size_t)CAP;
#pragma unroll
    for (int i = 0; i < 32; i++) {
        if (flags & (1u << i)) {
            if (pos < CAP) ib[pos] = (i >> 2) * 4096 + t * 4 + (i & 3);
            pos++;
        }
    }
    if (t == 0) scnt[row] = (total < CAP) ? total : CAP;
}

// =====================================================================
// Rescore via Z = Wk q: s_c = Z[row]·KB[idx_c]  (q·bk cancels in softmax)
// + softmax + weighted KB gather.
// =====================================================================
__global__ __launch_bounds__(256) void rescore_gather_kernel(
    const float* __restrict__ Z, const float* __restrict__ kb,
    const int* __restrict__ sidx, const int* __restrict__ scnt,
    __half* __restrict__ Th, __half* __restrict__ Tl)
{
    __shared__ float zs[H];
    __shared__ float sex[CAP];
    __shared__ int   idxs[CAP];
    __shared__ float red[8];
    const size_t row = blockIdx.x;
    const int t = threadIdx.x, lane = t & 31, wid = t >> 5;
    const int cnt = scnt[row];

#pragma unroll
    for (int j = 0; j < 4; j++) zs[t + j * 256] = Z[row * H + t + j * 256];
    for (int c = t; c < cnt; c += 256) idxs[c] = sidx[row * (size_t)CAP + c];
    __syncthreads();

    for (int c = wid; c < cnt; c += 8) {
        const float4* k4 = (const float4*)(kb + (size_t)idxs[c] * H);
        float s = 0.f;
#pragma unroll
        for (int j = lane; j < H / 4; j += 32) {
            const float4 k = k4[j];
            s += zs[4 * j] * k.x + zs[4 * j + 1] * k.y
               + zs[4 * j + 2] * k.z + zs[4 * j + 3] * k.w;
        }
#pragma unroll
        for (int o = 16; o; o >>= 1) s += __shfl_xor_sync(0xffffffffu, s, o);
        if (lane == 0) sex[c] = s;
    }
    __syncthreads();

    float mx = -1e30f;
    for (int c = t; c < cnt; c += 256) mx = fmaxf(mx, sex[c]);
#pragma unroll
    for (int o = 16; o; o >>= 1) mx = fmaxf(mx, __shfl_xor_sync(0xffffffffu, mx, o));
    if (lane == 0) red[wid] = mx;
    __syncthreads();
    if (t == 0) {
        float m = red[0];
#pragma unroll
        for (int i = 1; i < 8; i++) m = fmaxf(m, red[i]);
        red[0] = m;
    }
    __syncthreads();
    mx = red[0];
    __syncthreads();

    float ps = 0.f;
    for (int c = t; c < cnt; c += 256) {
        float e = __expf(sex[c] - mx);
        sex[c] = e;
        ps += e;
    }
#pragma unroll
    for (int o = 16; o; o >>= 1) ps += __shfl_xor_sync(0xffffffffu, ps, o);
    if (lane == 0) red[wid] = ps;
    __syncthreads();
    if (t == 0) {
        float s = 0.f;
#pragma unroll
        for (int i = 0; i < 8; i++) s += red[i];
        red[0] = s;
    }
    __syncthreads();
    const float inv = 1.0f / red[0];

    float a0 = 0.f, a1 = 0.f, a2 = 0.f, a3 = 0.f;
    for (int c = 0; c < cnt; c++) {
        const float w = sex[c] * inv;
        if (w < 5.96e-8f) continue;
        const float4 k4 = *(const float4*)&kb[(size_t)idxs[c] * H + t * 4];
        a0 += w * k4.x; a1 += w * k4.y; a2 += w * k4.z; a3 += w * k4.w;
    }
    __half2 h01, l01, h23, l23;
    split2(a0, a1, h01, l01);
    split2(a2, a3, h23, l23);
    uint2 uh, ul;
    uh.x = *(unsigned*)&h01; uh.y = *(unsigned*)&h23;
    ul.x = *(unsigned*)&l01; ul.y = *(unsigned*)&l23;
    *(uint2*)&Th[row * (size_t)H + t * 4] = uh;
    *(uint2*)&Tl[row * (size_t)H + t * 4] = ul;
}

} // namespace pks

#define PKS_SYM(p, s) { void* _t = nullptr; cudaGetSymbolAddress(&_t, s); p = (decltype(p))_t; }

extern "C" void kernel_launch(void* const* d_in, const int* in_sizes, int n_in,
                              void* d_out, int out_size) {
    using namespace pks;
    const float* q  = (const float*)d_in[0];
    const float* kb = (const float*)d_in[1];
    const float* Wk = (const float*)d_in[2];
    const float* bk = (const float*)d_in[3];
    const float* Wv = (const float*)d_in[4];
    const float* bv = (const float*)d_in[5];
    float* out = (float*)d_out;

    __half *qh, *ql, *kbh, *wkth, *wkh, *wkl, *wvth, *wvtl, *kh, *Th, *Tl, *Sh;
    float* Z;
    int *sidx, *scnt;
    PKS_SYM(qh, g_qh);      PKS_SYM(ql, g_ql);
    PKS_SYM(kbh, g_kbh);
    PKS_SYM(wkth, g_wkt_h);
    PKS_SYM(wkh, g_wk_h);   PKS_SYM(wkl, g_wk_l);
    PKS_SYM(wvth, g_wvt_h); PKS_SYM(wvtl, g_wvt_l);
    PKS_SYM(kh, g_kh);      PKS_SYM(Z, g_Z);
    PKS_SYM(Th, g_Th);      PKS_SYM(Tl, g_Tl);
    PKS_SYM(Sh, g_Sh);
    PKS_SYM(sidx, g_sidx);  PKS_SYM(scnt, g_scnt);

    const int smem3 = 2 * 4 * 128 * 40 * 2;   // 81920 (NPROD3, BK32, S2)
    const int smem2 = 2 * 3 * 128 * 40 * 2;   // 61440 (NPROD2, BK32, S2)
    const int smem1 = 2 * 2 * 128 * 72 * 2;   // 73728 (NPROD1, BK64, S2) keys + screen
    cudaFuncSetAttribute(gemm_tn<3, 2, 32, 2>, cudaFuncAttributeMaxDynamicSharedMemorySize, smem3);
    cudaFuncSetAttribute(gemm_tn<2, 2, 32, 2>, cudaFuncAttributeMaxDynamicSharedMemorySize, smem2);
    cudaFuncSetAttribute(gemm_tn<1, 1, 64, 2>, cudaFuncAttributeMaxDynamicSharedMemorySize, smem1);

    // 1) prep
    {
        int n4 = (int)(SZ_Q / 4);
        split_kernel<<<(n4 + 255) / 256, 256>>>((const float4*)q, (uint2*)qh, (uint2*)ql, n4);
    }
    {
        int n4 = (int)(SZ_KB / 4);
        tohalf_kernel<<<(n4 + 255) / 256, 256>>>((const float4*)kb, (uint2*)kbh, n4);
    }
    thalf_kernel<<<(H * QD + 255) / 256, 256>>>(Wk, wkth, H, QD);         // Wk^T fp16 [QD, H]
    {
        int n4 = (int)((size_t)H * QD / 4);                                // Wk split [H, QD] (as given)
        split_kernel<<<(n4 + 255) / 256, 256>>>((const float4*)Wk, (uint2*)wkh, (uint2*)wkl, n4);
    }
    tsplit_kernel<<<(H * H + 255) / 256, 256>>>(Wv, wvth, wvtl, H, H);    // Wv^T split [H, H]

    // 2) keys = KB @ Wk + bk (single product, fp16 out; screen only) [KS, QD]
    gemm_tn<1, 1, 64, 2><<<dim3(QD / 128, KS / 128), 256, smem1>>>(
        kbh, nullptr, wkth, nullptr, H, bk, nullptr, kh, nullptr, QD);

    // 3) Z = Q @ Wk^T (split-3, fp32, no bias — q·bk cancels in softmax) [MQ, H]
    gemm_tn<3, 2, 32, 2><<<dim3(H / 128, MQ / 128), 256, smem3>>>(
        qh, ql, wkh, wkl, QD, nullptr, Z, nullptr, nullptr, H);

    // 4) screen scores = qh @ kh^T (single product, BK64/S2, fp16 out) [MQ, KS]
    gemm_tn<1, 1, 64, 2><<<dim3(KS / 128, MQ / 128), 256, smem1>>>(
        qh, nullptr, kh, nullptr, QD, nullptr, nullptr, Sh, nullptr, KS);

    // 5) select candidates (s >= rowmax - 12.4)
    select_kernel<<<MQ, 1024>>>(Sh, sidx, scnt);

    // 6) rescore via Z·KB + softmax + weighted KB gather -> T split
    rescore_gather_kernel<<<MQ, 256>>>(Z, kb, sidx, scnt, Th, Tl);

    // 7) out = T @ Wv + bv (2-product split, fp32) [MQ, H]
    gemm_tn<2, 2, 32, 2><<<dim3(H / 128, MQ / 128), 256, smem2>>>(
        Th, Tl, wvth, wvtl, H, bv, out, nullptr, nullptr, H);
}